// round 15
// baseline (speedup 1.0000x reference)
#include <cuda_runtime.h>
#include <cuda_bf16.h>
#include <cstdint>

// ---------------- problem constants ----------------
// T=4, B=2, Ck=256, Cv=512, H=W=96, scales {1,2,3,6}, MAX=6, M=144, N=9216

// ---------------- device scratch (static, no allocation) ----------------
__device__ __align__(16) float g_pool6_k[2048 * 36];
__device__ __align__(16) float g_pool6_v[4096 * 36];
__device__ __align__(16) float g_convk[4 * 2 * 4 * 64 * 36];
__device__ __align__(16) float g_convv[4 * 2 * 4 * 128 * 36];
__device__ __align__(16) __nv_bfloat16 g_mkh[2 * 144 * 256];  // [b][m][c] hi (x Ck^-0.5)
__device__ __align__(16) __nv_bfloat16 g_mkl[2 * 144 * 256];  // lo
__device__ __align__(16) __nv_bfloat16 g_mvh[2 * 512 * 144];  // [b][v][m] hi
__device__ __align__(16) __nv_bfloat16 g_mvl[2 * 512 * 144];  // lo

__constant__ int c_scale[4] = {1, 2, 3, 6};
__constant__ int UI0[4][6] = {
    {0,0,0,0,0,0},
    {0,0,0,0,1,1},
    {0,0,0,1,1,2},
    {0,1,2,3,4,5}};
__constant__ int UI1[4][6] = {
    {0,0,0,0,0,0},
    {0,1,1,1,1,1},
    {0,1,1,2,2,2},
    {0,1,2,3,4,5}};
__constant__ float UW[4][6] = {
    {0.f,0.f,0.f,0.f,0.f,0.f},
    {0.f, 1.f/6.f, 0.5f, 5.f/6.f, 0.f, 0.f},
    {0.f, 0.25f, 0.75f, 0.25f, 0.75f, 0.f},
    {0.f,0.f,0.f,0.f,0.f,0.f}};

// ---------------- helpers ----------------
__device__ __forceinline__ void mma_bf16(float* d, const unsigned* a, const unsigned* b) {
    asm volatile(
        "mma.sync.aligned.m16n8k16.row.col.f32.bf16.bf16.f32 "
        "{%0,%1,%2,%3}, {%4,%5,%6,%7}, {%8,%9}, {%0,%1,%2,%3};"
        : "+f"(d[0]), "+f"(d[1]), "+f"(d[2]), "+f"(d[3])
        : "r"(a[0]), "r"(a[1]), "r"(a[2]), "r"(a[3]), "r"(b[0]), "r"(b[1]));
}
__device__ __forceinline__ void ldsm4(unsigned* r, uint32_t a) {
    asm volatile("ldmatrix.sync.aligned.m8n8.x4.shared.b16 {%0,%1,%2,%3}, [%4];"
                 : "=r"(r[0]), "=r"(r[1]), "=r"(r[2]), "=r"(r[3]) : "r"(a));
}
__device__ __forceinline__ void ldsm2(unsigned* r, uint32_t a) {
    asm volatile("ldmatrix.sync.aligned.m8n8.x2.shared.b16 {%0,%1}, [%2];"
                 : "=r"(r[0]), "=r"(r[1]) : "r"(a));
}
__device__ __forceinline__ void split_bf16(float x, __nv_bfloat16& hi, __nv_bfloat16& lo) {
    hi = __float2bfloat16(x);
    lo = __float2bfloat16(x - __bfloat162float(hi));
}
__device__ __forceinline__ unsigned packbf(__nv_bfloat16 l, __nv_bfloat16 h) {
    return ((unsigned)__bfloat16_as_ushort(h) << 16) | (unsigned)__bfloat16_as_ushort(l);
}

// ================= K1: 16x16 block means + qv passthrough copy =================
__global__ void k_pool(const float* __restrict__ mk, const float* __restrict__ mv,
                       const float* __restrict__ qv, float* __restrict__ out) {
    int p = blockIdx.x;
    int tid = threadIdx.x;
    if (p >= 6144) {
        int p2 = p - 6144;
        const float4* src = (const float4*)qv;
        float4* dst = (float4*)out;
        #pragma unroll
        for (int k = 0; k < 4; k++) {
            size_t f4 = (size_t)p2 * 1024 + tid + k * 256;
            size_t b = f4 / (512 * 2304);
            dst[f4 + b * 512 * 2304] = src[f4];
        }
        return;
    }
    const float* src; float* dst;
    if (p < 2048) { src = mk + (size_t)p * 9216; dst = g_pool6_k + (size_t)p * 36; }
    else { int q = p - 2048; src = mv + (size_t)q * 9216; dst = g_pool6_v + (size_t)q * 36; }
    __shared__ float rowsum[576];
    for (int task = tid; task < 576; task += 256) {
        int r = task / 6, j = task % 6;
        const float4* a = (const float4*)(src + r * 96 + j * 16);
        float4 v0 = a[0], v1 = a[1], v2 = a[2], v3 = a[3];
        rowsum[task] = (v0.x+v0.y+v0.z+v0.w) + (v1.x+v1.y+v1.z+v1.w)
                     + (v2.x+v2.y+v2.z+v2.w) + (v3.x+v3.y+v3.z+v3.w);
    }
    __syncthreads();
    if (tid < 36) {
        int by = tid / 6, bx = tid % 6;
        float s = 0.f;
        #pragma unroll
        for (int k = 0; k < 16; k++) s += rowsum[(by * 16 + k) * 6 + bx];
        dst[tid] = s * (1.0f / 256.0f);
    }
}

// ================= K2: 1x1 conv + bias + relu — weights read once per block =================
// grid 128 = kv(2) x tb(8) x si(4) x ohalf(2); 256 threads.
// smem: pooled[C][npos] (<= 512*36 floats = 73728 B, dynamic)
__global__ void k_conv(const float* __restrict__ kw, const float* __restrict__ kb,
                       const float* __restrict__ vw, const float* __restrict__ vb) {
    extern __shared__ float pooled[];
    int bi = blockIdx.x;
    int kv = bi >> 6;
    int tb = (bi >> 3) & 7;
    int si = (bi >> 1) & 3;
    int oh = bi & 1;
    int s = c_scale[si];
    int g = 6 / s;
    int npos = s * s;
    int C  = kv ? 512 : 256;
    int Co = kv ? 128 : 64;
    int t = tb >> 1;
    const float* p6 = (kv ? g_pool6_v : g_pool6_k) + (size_t)tb * C * 36;
    int tid = threadIdx.x;
    float ginv = 1.0f / (float)(g * g);

    // phase 1: pooled[c][pos] = mean of gxg block of the 6x6 grid
    for (int e = tid; e < C * npos; e += 256) {
        int c = e / npos, pos = e - c * npos;
        int pi = pos / s, pj = pos % s;
        const float* base = p6 + (size_t)c * 36 + (pi * g) * 6 + pj * g;
        float sum = 0.f;
        for (int a = 0; a < g; a++)
            for (int bb = 0; bb < g; bb++)
                sum += base[a * 6 + bb];
        pooled[c * npos + pos] = sum * ginv;
    }
    __syncthreads();

    // phase 2: each (o,pos) pair = full C-dot; lanes mostly share o -> w broadcast
    int Cohalf = Co >> 1;
    const float* wbase = (kv ? vw : kw) + (size_t)((t * 4 + si) * Co) * C;
    const float* bbase = (kv ? vb : kb) + (t * 4 + si) * Co;
    float* obase = (kv ? g_convv : g_convk) + (size_t)((tb * 4 + si) * Co) * 36;
    for (int pidx = tid; pidx < Cohalf * npos; pidx += 256) {
        int o_l = pidx / npos, pos = pidx - o_l * npos;
        int o = oh * Cohalf + o_l;
        const float4* wrow = (const float4*)(wbase + (size_t)o * C);
        float sum = 0.f;
        for (int c4 = 0; c4 < C / 4; c4++) {
            float4 wv = wrow[c4];
            int c = c4 * 4;
            sum += wv.x * pooled[c * npos + pos]
                 + wv.y * pooled[(c + 1) * npos + pos]
                 + wv.z * pooled[(c + 2) * npos + pos]
                 + wv.w * pooled[(c + 3) * npos + pos];
        }
        obase[(size_t)o * 36 + pos] = fmaxf(sum + bbase[o], 0.0f);
    }
}

// ================= K3: bilinear upsample + bf16 hi/lo layouts =================
__global__ void k_upsample() {
    int idx = blockIdx.x * 256 + threadIdx.x;
    if (idx >= 221184) return;
    if (idx < 73728) {
        int b = idx / (256 * 144);
        int rr = idx % (256 * 144);
        int c = rr / 144, m = rr % 144;
        int t = m / 36, pp = m % 36, i6 = pp / 6, j6 = pp % 6;
        int si = c >> 6, o = c & 63;
        int s = c_scale[si];
        const float* cv = g_convk + (size_t)(((t * 2 + b) * 4 + si) * 64 + o) * 36;
        int yi0 = UI0[si][i6], yi1 = UI1[si][i6]; float wy = UW[si][i6];
        int xi0 = UI0[si][j6], xi1 = UI1[si][j6]; float wx = UW[si][j6];
        float v00 = cv[yi0 * s + xi0], v01 = cv[yi0 * s + xi1];
        float v10 = cv[yi1 * s + xi0], v11 = cv[yi1 * s + xi1];
        float v = (1.f - wy) * ((1.f - wx) * v00 + wx * v01)
                +        wy  * ((1.f - wx) * v10 + wx * v11);
        v *= 0.0625f;
        __nv_bfloat16 hi, lo;
        split_bf16(v, hi, lo);
        size_t di = (size_t)(b * 144 + m) * 256 + c;
        g_mkh[di] = hi; g_mkl[di] = lo;
    } else {
        int r0 = idx - 73728;
        int b = r0 / (144 * 512);
        int rr = r0 % (144 * 512);
        int m = rr / 512, vch = rr % 512;
        int t = m / 36, pp = m % 36, i6 = pp / 6, j6 = pp % 6;
        int si = vch >> 7, o = vch & 127;
        int s = c_scale[si];
        const float* cv = g_convv + (size_t)(((t * 2 + b) * 4 + si) * 128 + o) * 36;
        int yi0 = UI0[si][i6], yi1 = UI1[si][i6]; float wy = UW[si][i6];
        int xi0 = UI0[si][j6], xi1 = UI1[si][j6]; float wx = UW[si][j6];
        float v00 = cv[yi0 * s + xi0], v01 = cv[yi0 * s + xi1];
        float v10 = cv[yi1 * s + xi0], v11 = cv[yi1 * s + xi1];
        float v = (1.f - wy) * ((1.f - wx) * v00 + wx * v01)
                +        wy  * ((1.f - wx) * v10 + wx * v11);
        __nv_bfloat16 hi, lo;
        split_bf16(v, hi, lo);
        size_t di = (size_t)(b * 512 + vch) * 144 + m;
        g_mvh[di] = hi; g_mvl[di] = lo;
    }
}

// ================= K4: tensor-core attention, reg-buffered staging + ldmatrix =================
// grid 144 = 2 b * 72 n-tiles of 128; 512 threads = 16 warps.
//
// smem byte layout:
//   QK phase : mkch_hi @0      [144m][40c]  11520
//              mkch_lo @11520               11520
//              qkT_hi  @23040  [128n][40c]  10240
//              qkT_lo  @33280               10240   (ends 43520)
//   AV phase : attT_hi @0      [128n][152m] 38912
//              attT_lo @38912               38912   (ends 77824)
//              mvch_hi @77824  [128r][56k]  14336   (48 valid k per stage, pitch 56)
//              mvch_lo @92160               14336   total 106496
__global__ __launch_bounds__(512, 1)
void k_attn(const float* __restrict__ qk, float* __restrict__ out) {
    extern __shared__ char smem[];
    uint32_t sbase = (uint32_t)__cvta_generic_to_shared(smem);
    __nv_bfloat16* attT_hi = (__nv_bfloat16*)(smem);
    __nv_bfloat16* attT_lo = (__nv_bfloat16*)(smem + 38912);
    __nv_bfloat16* mvch_hi = (__nv_bfloat16*)(smem + 77824);
    __nv_bfloat16* mvch_lo = (__nv_bfloat16*)(smem + 92160);
    __nv_bfloat16* mkch_hi = (__nv_bfloat16*)(smem);
    __nv_bfloat16* mkch_lo = (__nv_bfloat16*)(smem + 11520);
    __nv_bfloat16* qkT_hi  = (__nv_bfloat16*)(smem + 23040);
    __nv_bfloat16* qkT_lo  = (__nv_bfloat16*)(smem + 33280);

    int tid = threadIdx.x;
    int w = tid >> 5, lane = tid & 31;
    int g = lane >> 2, tq = lane & 3;
    int lane15 = lane & 15, lanehalf = (lane >> 4) & 1;
    int lane7 = lane & 7, laneb = (lane >> 3) & 1;
    int b = blockIdx.x / 72, ntile = blockIdx.x % 72;
    int n0 = ntile * 128;

    const float* qkb = qk + (size_t)b * 256 * 9216 + n0;

    // ---------------- phase 1: QK scores ----------------
    float acc[9][4];
    #pragma unroll
    for (int i = 0; i < 9; i++)
        #pragma unroll
        for (int j = 0; j < 4; j++) acc[i][j] = 0.f;

    int qn = tid & 127;
    int cb = (tid >> 7) * 2;
    float qcur[8], qnext[8];
    uint4 mkreg[3];

    // prologue: LDG mk(0) + qk(0) into regs, then STS
    #pragma unroll
    for (int i = 0; i < 3; i++) {
        int q = tid + i * 512;
        if (q < 1152) {
            int hl = q / 576, rem = q % 576;
            int m = rem % 144, part = rem / 144;
            mkreg[i] = *(const uint4*)((hl ? g_mkl : g_mkh)
                       + ((size_t)(b * 144 + m)) * 256 + part * 8);
        }
    }
    #pragma unroll
    for (int i = 0; i < 4; i++) {
        int row = cb + i * 8;
        qcur[2*i]   = qkb[(size_t)row * 9216 + qn];
        qcur[2*i+1] = qkb[(size_t)(row + 1) * 9216 + qn];
    }
    #pragma unroll
    for (int i = 0; i < 3; i++) {
        int q = tid + i * 512;
        if (q < 1152) {
            int hl = q / 576, rem = q % 576;
            int m = rem % 144, part = rem / 144;
            *(uint4*)((hl ? mkch_lo : mkch_hi) + m * 40 + part * 8) = mkreg[i];
        }
    }
    #pragma unroll
    for (int i = 0; i < 4; i++) {
        int c0 = cb + i * 8;
        __nv_bfloat16 h0, l0, h1, l1;
        split_bf16(qcur[2*i], h0, l0);
        split_bf16(qcur[2*i+1], h1, l1);
        *(unsigned*)(qkT_hi + qn * 40 + c0) = packbf(h0, h1);
        *(unsigned*)(qkT_lo + qn * 40 + c0) = packbf(l0, l1);
    }
    __syncthreads();

    for (int cc = 0; cc < 8; cc++) {
        // LDG next chunk into regs (hidden behind MMAs)
        if (cc < 7) {
            #pragma unroll
            for (int i = 0; i < 3; i++) {
                int q = tid + i * 512;
                if (q < 1152) {
                    int hl = q / 576, rem = q % 576;
                    int m = rem % 144, part = rem / 144;
                    mkreg[i] = *(const uint4*)((hl ? g_mkl : g_mkh)
                               + ((size_t)(b * 144 + m)) * 256 + (cc + 1) * 32 + part * 8);
                }
            }
            #pragma unroll
            for (int i = 0; i < 4; i++) {
                int row = (cc + 1) * 32 + cb + i * 8;
                qnext[2*i]   = qkb[(size_t)row * 9216 + qn];
                qnext[2*i+1] = qkb[(size_t)(row + 1) * 9216 + qn];
            }
        }
        // MMAs (ldmatrix frag loads — R13-proven addressing)
        #pragma unroll
        for (int kf = 0; kf < 2; kf++) {
            int kb0 = kf * 16;
            unsigned bh[2], bl[2];
            ldsm2(bh, sbase + 23040 + ((w * 8 + lane7) * 40 + kb0 + laneb * 8) * 2);
            ldsm2(bl, sbase + 33280 + ((w * 8 + lane7) * 40 + kb0 + laneb * 8) * 2);
            #pragma unroll
            for (int mf = 0; mf < 9; mf++) {
                unsigned ah[4], al[4];
                ldsm4(ah, sbase + ((mf * 16 + lane15) * 40 + kb0 + lanehalf * 8) * 2);
                ldsm4(al, sbase + 11520 + ((mf * 16 + lane15) * 40 + kb0 + lanehalf * 8) * 2);
                mma_bf16(acc[mf], ah, bh);
                mma_bf16(acc[mf], ah, bl);
                mma_bf16(acc[mf], al, bh);
            }
        }
        __syncthreads();
        // STS next chunk
        if (cc < 7) {
            #pragma unroll
            for (int i = 0; i < 3; i++) {
                int q = tid + i * 512;
                if (q < 1152) {
                    int hl = q / 576, rem = q % 576;
                    int m = rem % 144, part = rem / 144;
                    *(uint4*)((hl ? mkch_lo : mkch_hi) + m * 40 + part * 8) = mkreg[i];
                }
            }
            #pragma unroll
            for (int i = 0; i < 4; i++) {
                int c0 = cb + i * 8;
                __nv_bfloat16 h0, l0, h1, l1;
                split_bf16(qnext[2*i], h0, l0);
                split_bf16(qnext[2*i+1], h1, l1);
                *(unsigned*)(qkT_hi + qn * 40 + c0) = packbf(h0, h1);
                *(unsigned*)(qkT_lo + qn * 40 + c0) = packbf(l0, l1);
            }
            __syncthreads();
        }
    }
    __syncthreads();   // protect attT region (overlaps qkT) — all QK reads complete

    // ---------------- AV stage-0 LDG (overlaps softmax) ----------------
    uint4 mvreg[3];
    {
        #pragma unroll
        for (int it = 0; it < 3; it++) {
            int idx = tid + it * 512;
            int hl = idx / 768, rem = idx % 768;
            int r = rem / 6, part = rem % 6;
            int v = ((r >> 6) << 8) + (r & 63);   // p=0, ks=0
            mvreg[it] = *(const uint4*)((hl ? g_mvl : g_mvh)
                        + ((size_t)(b * 512 + v)) * 144 + part * 8);
        }
    }

    // ---------------- softmax over m (cols n = w*8 + 2tq + {0,1}) ----------------
    {
        float mx0 = -1e30f, mx1 = -1e30f;
        #pragma unroll
        for (int mf = 0; mf < 9; mf++) {
            mx0 = fmaxf(mx0, fmaxf(acc[mf][0], acc[mf][2]));
            mx1 = fmaxf(mx1, fmaxf(acc[mf][1], acc[mf][3]));
        }
        #pragma unroll
        for (int off = 4; off <= 16; off <<= 1) {
            mx0 = fmaxf(mx0, __shfl_xor_sync(0xffffffffu, mx0, off));
            mx1 = fmaxf(mx1, __shfl_xor_sync(0xffffffffu, mx1, off));
        }
        float s0 = 0.f, s1 = 0.f;
        #pragma unroll
        for (int mf = 0; mf < 9; mf++) {
            acc[mf][0] = __expf(acc[mf][0] - mx0);
            acc[mf][1] = __expf(acc[mf][1] - mx1);
            acc[mf][2] = __expf(acc[mf][2] - mx0);
            acc[mf][3] = __expf(acc[mf][3] - mx1);
            s0 += acc[mf][0] + acc[mf][2];
            s1 += acc[mf][1] + acc[mf][3];
        }
        #pragma unroll
        for (int off = 4; off <= 16; off <<= 1) {
            s0 += __shfl_xor_sync(0xffffffffu, s0, off);
            s1 += __shfl_xor_sync(0xffffffffu, s1, off);
        }
        float in0 = 1.0f / s0, in1 = 1.0f / s1;
        int ncol0 = w * 8 + 2 * tq, ncol1 = ncol0 + 1;
        #pragma unroll
        for (int mf = 0; mf < 9; mf++) {
            int m0 = mf * 16 + g, m1 = m0 + 8;
            __nv_bfloat16 hi, lo;
            split_bf16(acc[mf][0] * in0, hi, lo);
            attT_hi[ncol0 * 152 + m0] = hi; attT_lo[ncol0 * 152 + m0] = lo;
            split_bf16(acc[mf][1] * in1, hi, lo);
            attT_hi[ncol1 * 152 + m0] = hi; attT_lo[ncol1 * 152 + m0] = lo;
            split_bf16(acc[mf][2] * in0, hi, lo);
            attT_hi[ncol0 * 152 + m1] = hi; attT_lo[ncol0 * 152 + m1] = lo;
            split_bf16(acc[mf][3] * in1, hi, lo);
            attT_hi[ncol1 * 152 + m1] = hi; attT_lo[ncol1 * 152 + m1] = lo;
        }
    }

    // STS stage 0
    #pragma unroll
    for (int it = 0; it < 3; it++) {
        int idx = tid + it * 512;
        int hl = idx / 768, rem = idx % 768;
        int r = rem / 6, part = rem % 6;
        *(uint4*)((hl ? mvch_lo : mvch_hi) + r * 56 + part * 8) = mvreg[it];
    }
    __syncthreads();

    // ---------------- phase 2: AV, 12 stages of 48k (4 p-passes x 3) ----------------
    int mfa = w & 7;
    int vhalf = w >> 3;
    float acc2[8][4];
    for (int s = 0; s < 12; s++) {
        int p = s / 3, kq = s % 3, ks = kq * 48;
        if (kq == 0) {
            #pragma unroll
            for (int j = 0; j < 8; j++)
                #pragma unroll
                for (int q = 0; q < 4; q++) acc2[j][q] = 0.f;
        }
        // LDG next stage into regs (hidden behind MMAs)
        if (s < 11) {
            int p1 = (s + 1) / 3, ks1 = ((s + 1) % 3) * 48;
            #pragma unroll
            for (int it = 0; it < 3; it++) {
                int idx = tid + it * 512;
                int hl = idx / 768, rem = idx % 768;
                int r = rem / 6, part = rem % 6;
                int v = ((r >> 6) << 8) + p1 * 64 + (r & 63);
                mvreg[it] = *(const uint4*)((hl ? g_mvl : g_mvh)
                            + ((size_t)(b * 512 + v)) * 144 + ks1 + part * 8);
            }
        }
        // MMAs on current stage: 3 k-frags of 16 (ldmatrix)
        #pragma unroll
        for (int kfi = 0; kfi < 3; kfi++) {
            int kb0 = ks + kfi * 16;           // absolute k for attT
            int kl0 = kfi * 16;                // stage-local k for mvch
            unsigned ah[4], al[4];
            ldsm4(ah, sbase + ((mfa * 16 + lane15) * 152 + kb0 + lanehalf * 8) * 2);
            ldsm4(al, sbase + 38912 + ((mfa * 16 + lane15) * 152 + kb0 + lanehalf * 8) * 2);
            #pragma unroll
            for (int j = 0; j < 8; j++) {
                int r = vhalf * 64 + j * 8 + lane7;
                unsigned bh[2], bl[2];
                ldsm2(bh, sbase + 77824 + (r * 56 + kl0 + laneb * 8) * 2);
                ldsm2(bl, sbase + 92160 + (r * 56 + kl0 + laneb * 8) * 2);
                mma_bf16(acc2[j], ah, bh);
                mma_bf16(acc2[j], ah, bl);
                mma_bf16(acc2[j], al, bh);
            }
        }
        __syncthreads();
        // epilogue at end of each p-pass
        if (kq == 2) {
            #pragma unroll
            for (int j = 0; j < 8; j++) {
                int v = vhalf * 256 + p * 64 + j * 8 + 2 * tq;
                float* p0 = out + (size_t)(b * 1024 + 512 + v) * 9216 + n0 + 16 * mfa + g;
                p0[0]        = acc2[j][0];
                p0[8]        = acc2[j][2];
                p0[9216]     = acc2[j][1];
                p0[9216 + 8] = acc2[j][3];
            }
        }
        // STS next stage
        if (s < 11) {
            #pragma unroll
            for (int it = 0; it < 3; it++) {
                int idx = tid + it * 512;
                int hl = idx / 768, rem = idx % 768;
                int r = rem / 6, part = rem % 6;
                *(uint4*)((hl ? mvch_lo : mvch_hi) + r * 56 + part * 8) = mvreg[it];
            }
            __syncthreads();
        }
    }
}

// ================= launch =================
extern "C" void kernel_launch(void* const* d_in, const int* in_sizes, int n_in,
                              void* d_out, int out_size) {
    const float* mk = (const float*)d_in[0];
    const float* mv = (const float*)d_in[1];
    const float* qk = (const float*)d_in[2];
    const float* qv = (const float*)d_in[3];
    const float* kw = (const float*)d_in[4];
    const float* kb = (const float*)d_in[5];
    const float* vw = (const float*)d_in[6];
    const float* vb = (const float*)d_in[7];
    float* out = (float*)d_out;

    // 2048 key planes + 4096 value planes + 2304 qv-copy blocks
    k_pool<<<8448, 256>>>(mk, mv, qv, out);
    cudaFuncSetAttribute(k_conv, cudaFuncAttributeMaxDynamicSharedMemorySize, 73728);
    k_conv<<<128, 256, 73728>>>(kw, kb, vw, vb);
    k_upsample<<<864, 256>>>();
    cudaFuncSetAttribute(k_attn, cudaFuncAttributeMaxDynamicSharedMemorySize, 106496);
    k_attn<<<144, 512, 106496>>>(qk, out);
}

// round 16
// speedup vs baseline: 2.0467x; 2.0467x over previous
#include <cuda_runtime.h>
#include <cuda_bf16.h>
#include <cstdint>

// ---------------- problem constants ----------------
// T=4, B=2, Ck=256, Cv=512, H=W=96, scales {1,2,3,6}, MAX=6, M=144, N=9216

// ---------------- device scratch (static, no allocation) ----------------
__device__ __align__(16) float g_pool6_k[2048 * 36];
__device__ __align__(16) float g_pool6_v[4096 * 36];
__device__ __align__(16) float g_convk[4 * 2 * 4 * 64 * 36];
__device__ __align__(16) float g_convv[4 * 2 * 4 * 128 * 36];
__device__ __align__(16) __nv_bfloat16 g_mkh[2 * 144 * 256];  // [b][m][c] hi (x Ck^-0.5)
__device__ __align__(16) __nv_bfloat16 g_mkl[2 * 144 * 256];  // lo
__device__ __align__(16) __nv_bfloat16 g_mvh[2 * 512 * 144];  // [b][v][m] hi
__device__ __align__(16) __nv_bfloat16 g_mvl[2 * 512 * 144];  // lo

__constant__ int c_scale[4] = {1, 2, 3, 6};
__constant__ int UI0[4][6] = {
    {0,0,0,0,0,0},
    {0,0,0,0,1,1},
    {0,0,0,1,1,2},
    {0,1,2,3,4,5}};
__constant__ int UI1[4][6] = {
    {0,0,0,0,0,0},
    {0,1,1,1,1,1},
    {0,1,1,2,2,2},
    {0,1,2,3,4,5}};
__constant__ float UW[4][6] = {
    {0.f,0.f,0.f,0.f,0.f,0.f},
    {0.f, 1.f/6.f, 0.5f, 5.f/6.f, 0.f, 0.f},
    {0.f, 0.25f, 0.75f, 0.25f, 0.75f, 0.f},
    {0.f,0.f,0.f,0.f,0.f,0.f}};

// ---------------- helpers ----------------
__device__ __forceinline__ void mma_bf16(float* d, const unsigned* a, const unsigned* b) {
    asm volatile(
        "mma.sync.aligned.m16n8k16.row.col.f32.bf16.bf16.f32 "
        "{%0,%1,%2,%3}, {%4,%5,%6,%7}, {%8,%9}, {%0,%1,%2,%3};"
        : "+f"(d[0]), "+f"(d[1]), "+f"(d[2]), "+f"(d[3])
        : "r"(a[0]), "r"(a[1]), "r"(a[2]), "r"(a[3]), "r"(b[0]), "r"(b[1]));
}
__device__ __forceinline__ void split_bf16(float x, __nv_bfloat16& hi, __nv_bfloat16& lo) {
    hi = __float2bfloat16(x);
    lo = __float2bfloat16(x - __bfloat162float(hi));
}
__device__ __forceinline__ unsigned packbf(__nv_bfloat16 l, __nv_bfloat16 h) {
    return ((unsigned)__bfloat16_as_ushort(h) << 16) | (unsigned)__bfloat16_as_ushort(l);
}

// ================= K1: 16x16 block means + qv passthrough copy =================
__global__ void k_pool(const float* __restrict__ mk, const float* __restrict__ mv,
                       const float* __restrict__ qv, float* __restrict__ out) {
    int p = blockIdx.x;
    int tid = threadIdx.x;
    if (p >= 6144) {
        int p2 = p - 6144;
        const float4* src = (const float4*)qv;
        float4* dst = (float4*)out;
        #pragma unroll
        for (int k = 0; k < 4; k++) {
            size_t f4 = (size_t)p2 * 1024 + tid + k * 256;
            size_t b = f4 / (512 * 2304);
            dst[f4 + b * 512 * 2304] = src[f4];
        }
        return;
    }
    const float* src; float* dst;
    if (p < 2048) { src = mk + (size_t)p * 9216; dst = g_pool6_k + (size_t)p * 36; }
    else { int q = p - 2048; src = mv + (size_t)q * 9216; dst = g_pool6_v + (size_t)q * 36; }
    __shared__ float rowsum[576];
    for (int task = tid; task < 576; task += 256) {
        int r = task / 6, j = task % 6;
        const float4* a = (const float4*)(src + r * 96 + j * 16);
        float4 v0 = a[0], v1 = a[1], v2 = a[2], v3 = a[3];
        rowsum[task] = (v0.x+v0.y+v0.z+v0.w) + (v1.x+v1.y+v1.z+v1.w)
                     + (v2.x+v2.y+v2.z+v2.w) + (v3.x+v3.y+v3.z+v3.w);
    }
    __syncthreads();
    if (tid < 36) {
        int by = tid / 6, bx = tid % 6;
        float s = 0.f;
        #pragma unroll
        for (int k = 0; k < 16; k++) s += rowsum[(by * 16 + k) * 6 + bx];
        dst[tid] = s * (1.0f / 256.0f);
    }
}

// ================= K2: per-(t,b,scale,pos) 1x1 conv + bias + relu (R14-proven) =================
__global__ void k_conv(const float* __restrict__ kw, const float* __restrict__ kb,
                       const float* __restrict__ vw, const float* __restrict__ vb) {
    __shared__ float pooled[512];
    int bi = blockIdx.x;
    int kv = bi / 400;
    int rem = bi % 400;
    int tb = rem / 50;
    int task = rem % 50;
    int si, pos;
    if (task < 1)       { si = 0; pos = 0; }
    else if (task < 5)  { si = 1; pos = task - 1; }
    else if (task < 14) { si = 2; pos = task - 5; }
    else                { si = 3; pos = task - 14; }
    int s = c_scale[si];
    int g = 6 / s;
    int pi = pos / s, pj = pos % s;
    int C  = kv ? 512 : 256;
    int Co = kv ? 128 : 64;
    const float* p6 = kv ? g_pool6_v : g_pool6_k;
    int tid = threadIdx.x;
    float ginv = 1.0f / (float)(g * g);
    for (int c = tid; c < C; c += 256) {
        const float* pp = p6 + (size_t)(tb * C + c) * 36;
        float sum = 0.f;
        for (int a = 0; a < g; a++)
            for (int bb = 0; bb < g; bb++)
                sum += pp[(pi * g + a) * 6 + (pj * g + bb)];
        pooled[c] = sum * ginv;
    }
    __syncthreads();
    int t = tb >> 1;
    int L = 256 / Co;
    int o = tid / L, r = tid % L;
    int chunk = C / L;
    const float* w = (kv ? vw : kw) + (size_t)((t * 4 + si) * Co + o) * C + r * chunk;
    const float* pl = pooled + r * chunk;
    float partial = 0.f;
    for (int i = 0; i < chunk; i += 4) {
        float4 wv = *(const float4*)(w + i);
        float4 pv = *(const float4*)(pl + i);
        partial += wv.x * pv.x + wv.y * pv.y + wv.z * pv.z + wv.w * pv.w;
    }
    for (int off = 1; off < L; off <<= 1)
        partial += __shfl_xor_sync(0xffffffffu, partial, off);
    if (r == 0) {
        float bias = (kv ? vb : kb)[(t * 4 + si) * Co + o];
        float v = fmaxf(partial + bias, 0.0f);
        float* cdst = (kv ? g_convv : g_convk) + (size_t)((tb * 4 + si) * Co + o) * 36 + pos;
        *cdst = v;
    }
}

// ================= K3: bilinear upsample + bf16 hi/lo layouts =================
__global__ void k_upsample() {
    int idx = blockIdx.x * 256 + threadIdx.x;
    if (idx >= 221184) return;
    if (idx < 73728) {
        int b = idx / (256 * 144);
        int rr = idx % (256 * 144);
        int c = rr / 144, m = rr % 144;
        int t = m / 36, pp = m % 36, i6 = pp / 6, j6 = pp % 6;
        int si = c >> 6, o = c & 63;
        int s = c_scale[si];
        const float* cv = g_convk + (size_t)(((t * 2 + b) * 4 + si) * 64 + o) * 36;
        int yi0 = UI0[si][i6], yi1 = UI1[si][i6]; float wy = UW[si][i6];
        int xi0 = UI0[si][j6], xi1 = UI1[si][j6]; float wx = UW[si][j6];
        float v00 = cv[yi0 * s + xi0], v01 = cv[yi0 * s + xi1];
        float v10 = cv[yi1 * s + xi0], v11 = cv[yi1 * s + xi1];
        float v = (1.f - wy) * ((1.f - wx) * v00 + wx * v01)
                +        wy  * ((1.f - wx) * v10 + wx * v11);
        v *= 0.0625f;
        __nv_bfloat16 hi, lo;
        split_bf16(v, hi, lo);
        size_t di = (size_t)(b * 144 + m) * 256 + c;
        g_mkh[di] = hi; g_mkl[di] = lo;
    } else {
        int r0 = idx - 73728;
        int b = r0 / (144 * 512);
        int rr = r0 % (144 * 512);
        int m = rr / 512, vch = rr % 512;
        int t = m / 36, pp = m % 36, i6 = pp / 6, j6 = pp % 6;
        int si = vch >> 7, o = vch & 127;
        int s = c_scale[si];
        const float* cv = g_convv + (size_t)(((t * 2 + b) * 4 + si) * 128 + o) * 36;
        int yi0 = UI0[si][i6], yi1 = UI1[si][i6]; float wy = UW[si][i6];
        int xi0 = UI0[si][j6], xi1 = UI1[si][j6]; float wx = UW[si][j6];
        float v00 = cv[yi0 * s + xi0], v01 = cv[yi0 * s + xi1];
        float v10 = cv[yi1 * s + xi0], v11 = cv[yi1 * s + xi1];
        float v = (1.f - wy) * ((1.f - wx) * v00 + wx * v01)
                +        wy  * ((1.f - wx) * v10 + wx * v11);
        __nv_bfloat16 hi, lo;
        split_bf16(v, hi, lo);
        size_t di = (size_t)(b * 512 + vch) * 144 + m;
        g_mvh[di] = hi; g_mvl[di] = lo;
    }
}

// ================= K4: tensor-core attention — 2 CTAs/SM, R14 per-warp math =================
// grid 288 = 2 b * 144 n-tiles of 64; 256 threads = 8 warps; 2 CTAs co-resident per SM.
//
// smem byte layout (per CTA, total 67584):
//   QK phase : mkch_hi @0      [144m][40c]  11520
//              mkch_lo @11520               11520
//              qkT_hi  @23040  [64n][40c]    5120
//              qkT_lo  @28160                5120   (ends 33280)
//   AV phase : attT_hi @0      [64n][152m]  19456
//              attT_lo @19456               19456   (ends 38912)
//              mvch_hi @38912  [128r][56k]  14336   (48 valid k per stage)
//              mvch_lo @53248               14336   (ends 67584)
__global__ __launch_bounds__(256, 2)
void k_attn(const float* __restrict__ qk, float* __restrict__ out) {
    extern __shared__ char smem[];
    __nv_bfloat16* attT_hi = (__nv_bfloat16*)(smem);
    __nv_bfloat16* attT_lo = (__nv_bfloat16*)(smem + 19456);
    __nv_bfloat16* mvch_hi = (__nv_bfloat16*)(smem + 38912);
    __nv_bfloat16* mvch_lo = (__nv_bfloat16*)(smem + 53248);
    __nv_bfloat16* mkch_hi = (__nv_bfloat16*)(smem);
    __nv_bfloat16* mkch_lo = (__nv_bfloat16*)(smem + 11520);
    __nv_bfloat16* qkT_hi  = (__nv_bfloat16*)(smem + 23040);
    __nv_bfloat16* qkT_lo  = (__nv_bfloat16*)(smem + 28160);

    int tid = threadIdx.x;
    int w = tid >> 5, lane = tid & 31;     // 8 warps
    int g = lane >> 2, tq = lane & 3;
    int b = blockIdx.x / 144, ntile = blockIdx.x % 144;
    int n0 = ntile * 64;

    const float* qkb = qk + (size_t)b * 256 * 9216 + n0;

    // ---------------- phase 1: QK scores [144m x 64n] ----------------
    float acc[9][4];
    #pragma unroll
    for (int i = 0; i < 9; i++)
        #pragma unroll
        for (int j = 0; j < 4; j++) acc[i][j] = 0.f;

    // qk register prefetch: thread owns column qn (64), c-base cb in {0,2,4,6}
    int qn = tid & 63;
    int cb = (tid >> 6) * 2;
    float qcur[8], qnext[8];
    uint4 mkreg[5];

    // prologue: LDG mk(0) + qk(0) into regs, then STS
    #pragma unroll
    for (int i = 0; i < 5; i++) {
        int q = tid + i * 256;
        if (q < 1152) {
            int hl = q / 576, rem = q % 576;
            int m = rem % 144, part = rem / 144;
            mkreg[i] = *(const uint4*)((hl ? g_mkl : g_mkh)
                       + ((size_t)(b * 144 + m)) * 256 + part * 8);
        }
    }
    #pragma unroll
    for (int i = 0; i < 4; i++) {
        int row = cb + i * 8;
        qcur[2*i]   = qkb[(size_t)row * 9216 + qn];
        qcur[2*i+1] = qkb[(size_t)(row + 1) * 9216 + qn];
    }
    #pragma unroll
    for (int i = 0; i < 5; i++) {
        int q = tid + i * 256;
        if (q < 1152) {
            int hl = q / 576, rem = q % 576;
            int m = rem % 144, part = rem / 144;
            *(uint4*)((hl ? mkch_lo : mkch_hi) + m * 40 + part * 8) = mkreg[i];
        }
    }
    #pragma unroll
    for (int i = 0; i < 4; i++) {
        int c0 = cb + i * 8;
        __nv_bfloat16 h0, l0, h1, l1;
        split_bf16(qcur[2*i], h0, l0);
        split_bf16(qcur[2*i+1], h1, l1);
        *(unsigned*)(qkT_hi + qn * 40 + c0) = packbf(h0, h1);
        *(unsigned*)(qkT_lo + qn * 40 + c0) = packbf(l0, l1);
    }
    __syncthreads();

    for (int cc = 0; cc < 8; cc++) {
        // LDG next chunk into regs (hidden behind MMAs)
        if (cc < 7) {
            #pragma unroll
            for (int i = 0; i < 5; i++) {
                int q = tid + i * 256;
                if (q < 1152) {
                    int hl = q / 576, rem = q % 576;
                    int m = rem % 144, part = rem / 144;
                    mkreg[i] = *(const uint4*)((hl ? g_mkl : g_mkh)
                               + ((size_t)(b * 144 + m)) * 256 + (cc + 1) * 32 + part * 8);
                }
            }
            #pragma unroll
            for (int i = 0; i < 4; i++) {
                int row = (cc + 1) * 32 + cb + i * 8;
                qnext[2*i]   = qkb[(size_t)row * 9216 + qn];
                qnext[2*i+1] = qkb[(size_t)(row + 1) * 9216 + qn];
            }
        }
        // MMAs (scalar frag loads, R14-proven addressing)
        #pragma unroll
        for (int kf = 0; kf < 2; kf++) {
            int kb0 = kf * 16 + 2 * tq;
            unsigned bh[2], bl[2];
            const __nv_bfloat16* brow = qkT_hi + (w * 8 + g) * 40 + kb0;
            bh[0] = *(const unsigned*)(brow);
            bh[1] = *(const unsigned*)(brow + 8);
            const __nv_bfloat16* brol = qkT_lo + (w * 8 + g) * 40 + kb0;
            bl[0] = *(const unsigned*)(brol);
            bl[1] = *(const unsigned*)(brol + 8);
            #pragma unroll
            for (int mf = 0; mf < 9; mf++) {
                const __nv_bfloat16* ah0 = mkch_hi + (mf * 16 + g) * 40 + kb0;
                const __nv_bfloat16* al0 = mkch_lo + (mf * 16 + g) * 40 + kb0;
                unsigned ah[4], al[4];
                ah[0] = *(const unsigned*)(ah0);
                ah[1] = *(const unsigned*)(ah0 + 8 * 40);
                ah[2] = *(const unsigned*)(ah0 + 8);
                ah[3] = *(const unsigned*)(ah0 + 8 * 40 + 8);
                al[0] = *(const unsigned*)(al0);
                al[1] = *(const unsigned*)(al0 + 8 * 40);
                al[2] = *(const unsigned*)(al0 + 8);
                al[3] = *(const unsigned*)(al0 + 8 * 40 + 8);
                mma_bf16(acc[mf], ah, bh);
                mma_bf16(acc[mf], ah, bl);
                mma_bf16(acc[mf], al, bh);
            }
        }
        __syncthreads();
        // STS next chunk
        if (cc < 7) {
            #pragma unroll
            for (int i = 0; i < 5; i++) {
                int q = tid + i * 256;
                if (q < 1152) {
                    int hl = q / 576, rem = q % 576;
                    int m = rem % 144, part = rem / 144;
                    *(uint4*)((hl ? mkch_lo : mkch_hi) + m * 40 + part * 8) = mkreg[i];
                }
            }
            #pragma unroll
            for (int i = 0; i < 4; i++) {
                int c0 = cb + i * 8;
                __nv_bfloat16 h0, l0, h1, l1;
                split_bf16(qnext[2*i], h0, l0);
                split_bf16(qnext[2*i+1], h1, l1);
                *(unsigned*)(qkT_hi + qn * 40 + c0) = packbf(h0, h1);
                *(unsigned*)(qkT_lo + qn * 40 + c0) = packbf(l0, l1);
            }
            __syncthreads();
        }
    }
    __syncthreads();   // protect attT region (overlaps mkch/qkT) — all QK reads complete

    // ---------------- AV stage-0 LDG (overlaps softmax) ----------------
    uint4 mvreg[6];
    {
        #pragma unroll
        for (int it = 0; it < 6; it++) {
            int idx = tid + it * 256;          // 1536 uint4 per 48k stage
            int hl = idx / 768, rem = idx % 768;
            int r = rem / 6, part = rem % 6;
            int v = ((r >> 6) << 8) + (r & 63);   // p=0, ks=0
            mvreg[it] = *(const uint4*)((hl ? g_mvl : g_mvh)
                        + ((size_t)(b * 512 + v)) * 144 + part * 8);
        }
    }

    // ---------------- softmax over m (cols n = w*8 + 2tq + {0,1}) ----------------
    {
        float mx0 = -1e30f, mx1 = -1e30f;
        #pragma unroll
        for (int mf = 0; mf < 9; mf++) {
            mx0 = fmaxf(mx0, fmaxf(acc[mf][0], acc[mf][2]));
            mx1 = fmaxf(mx1, fmaxf(acc[mf][1], acc[mf][3]));
        }
        #pragma unroll
        for (int off = 4; off <= 16; off <<= 1) {
            mx0 = fmaxf(mx0, __shfl_xor_sync(0xffffffffu, mx0, off));
            mx1 = fmaxf(mx1, __shfl_xor_sync(0xffffffffu, mx1, off));
        }
        float s0 = 0.f, s1 = 0.f;
        #pragma unroll
        for (int mf = 0; mf < 9; mf++) {
            acc[mf][0] = __expf(acc[mf][0] - mx0);
            acc[mf][1] = __expf(acc[mf][1] - mx1);
            acc[mf][2] = __expf(acc[mf][2] - mx0);
            acc[mf][3] = __expf(acc[mf][3] - mx1);
            s0 += acc[mf][0] + acc[mf][2];
            s1 += acc[mf][1] + acc[mf][3];
        }
        #pragma unroll
        for (int off = 4; off <= 16; off <<= 1) {
            s0 += __shfl_xor_sync(0xffffffffu, s0, off);
            s1 += __shfl_xor_sync(0xffffffffu, s1, off);
        }
        float in0 = 1.0f / s0, in1 = 1.0f / s1;
        int ncol0 = w * 8 + 2 * tq, ncol1 = ncol0 + 1;
        #pragma unroll
        for (int mf = 0; mf < 9; mf++) {
            int m0 = mf * 16 + g, m1 = m0 + 8;
            __nv_bfloat16 hi, lo;
            split_bf16(acc[mf][0] * in0, hi, lo);
            attT_hi[ncol0 * 152 + m0] = hi; attT_lo[ncol0 * 152 + m0] = lo;
            split_bf16(acc[mf][1] * in1, hi, lo);
            attT_hi[ncol1 * 152 + m0] = hi; attT_lo[ncol1 * 152 + m0] = lo;
            split_bf16(acc[mf][2] * in0, hi, lo);
            attT_hi[ncol0 * 152 + m1] = hi; attT_lo[ncol0 * 152 + m1] = lo;
            split_bf16(acc[mf][3] * in1, hi, lo);
            attT_hi[ncol1 * 152 + m1] = hi; attT_lo[ncol1 * 152 + m1] = lo;
        }
    }

    // STS stage 0
    #pragma unroll
    for (int it = 0; it < 6; it++) {
        int idx = tid + it * 256;
        int hl = idx / 768, rem = idx % 768;
        int r = rem / 6, part = rem % 6;
        *(uint4*)((hl ? mvch_lo : mvch_hi) + r * 56 + part * 8) = mvreg[it];
    }
    __syncthreads();

    // ---------------- phase 2: AV, 12 stages of 48k (4 p-passes x 3) ----------------
    int mfa = w & 3;       // output n-frag (4 frags of 16 rows = 64n)
    int vhalf = w >> 2;    // which 64-row half of the staged 128 rows
    float acc2[8][4];
    for (int s = 0; s < 12; s++) {
        int p = s / 3, kq = s % 3, ks = kq * 48;
        if (kq == 0) {
            #pragma unroll
            for (int j = 0; j < 8; j++)
                #pragma unroll
                for (int q = 0; q < 4; q++) acc2[j][q] = 0.f;
        }
        // LDG next stage into regs (hidden behind MMAs)
        if (s < 11) {
            int p1 = (s + 1) / 3, ks1 = ((s + 1) % 3) * 48;
            #pragma unroll
            for (int it = 0; it < 6; it++) {
                int idx = tid + it * 256;
                int hl = idx / 768, rem = idx % 768;
                int r = rem / 6, part = rem % 6;
                int v = ((r >> 6) << 8) + p1 * 64 + (r & 63);
                mvreg[it] = *(const uint4*)((hl ? g_mvl : g_mvh)
                            + ((size_t)(b * 512 + v)) * 144 + ks1 + part * 8);
            }
        }
        // MMAs on current stage: 3 k-frags of 16 (scalar frag loads)
        #pragma unroll
        for (int kfi = 0; kfi < 3; kfi++) {
            int kb0 = ks + kfi * 16 + 2 * tq;          // absolute k for attT
            int kl0 = kfi * 16 + 2 * tq;               // stage-local k for mvch
            const __nv_bfloat16* ah0 = attT_hi + (mfa * 16 + g) * 152 + kb0;
            const __nv_bfloat16* al0 = attT_lo + (mfa * 16 + g) * 152 + kb0;
            unsigned ah[4], al[4];
            ah[0] = *(const unsigned*)(ah0);
            ah[1] = *(const unsigned*)(ah0 + 8 * 152);
            ah[2] = *(const unsigned*)(ah0 + 8);
            ah[3] = *(const unsigned*)(ah0 + 8 * 152 + 8);
            al[0] = *(const unsigned*)(al0);
            al[1] = *(const unsigned*)(al0 + 8 * 152);
            al[2] = *(const unsigned*)(al0 + 8);
            al[3] = *(const unsigned*)(al0 + 8 * 152 + 8);
            #pragma unroll
            for (int j = 0; j < 8; j++) {
                int r = vhalf * 64 + j * 8 + g;
                unsigned bh[2], bl[2];
                const __nv_bfloat16* brow = mvch_hi + r * 56 + kl0;
                bh[0] = *(const unsigned*)(brow);
                bh[1] = *(const unsigned*)(brow + 8);
                const __nv_bfloat16* brol = mvch_lo + r * 56 + kl0;
                bl[0] = *(const unsigned*)(brol);
                bl[1] = *(const unsigned*)(brol + 8);
                mma_bf16(acc2[j], ah, bh);
                mma_bf16(acc2[j], ah, bl);
                mma_bf16(acc2[j], al, bh);
            }
        }
        __syncthreads();   // all warps done reading current stage
        // epilogue at end of each p-pass
        if (kq == 2) {
            #pragma unroll
            for (int j = 0; j < 8; j++) {
                int v = vhalf * 256 + p * 64 + j * 8 + 2 * tq;
                float* p0 = out + (size_t)(b * 1024 + 512 + v) * 9216 + n0 + 16 * mfa + g;
                p0[0]        = acc2[j][0];
                p0[8]        = acc2[j][2];
                p0[9216]     = acc2[j][1];
                p0[9216 + 8] = acc2[j][3];
            }
        }
        // STS next stage
        if (s < 11) {
            #pragma unroll
            for (int it = 0; it < 6; it++) {
                int idx = tid + it * 256;
                int hl = idx / 768, rem = idx % 768;
                int r = rem / 6, part = rem % 6;
                *(uint4*)((hl ? mvch_lo : mvch_hi) + r * 56 + part * 8) = mvreg[it];
            }
            __syncthreads();
        }
    }
}

// ================= launch =================
extern "C" void kernel_launch(void* const* d_in, const int* in_sizes, int n_in,
                              void* d_out, int out_size) {
    const float* mk = (const float*)d_in[0];
    const float* mv = (const float*)d_in[1];
    const float* qk = (const float*)d_in[2];
    const float* qv = (const float*)d_in[3];
    const float* kw = (const float*)d_in[4];
    const float* kb = (const float*)d_in[5];
    const float* vw = (const float*)d_in[6];
    const float* vb = (const float*)d_in[7];
    float* out = (float*)d_out;

    // 2048 key planes + 4096 value planes + 2304 qv-copy blocks
    k_pool<<<8448, 256>>>(mk, mv, qv, out);
    k_conv<<<800, 256>>>(kw, kb, vw, vb);
    k_upsample<<<864, 256>>>();
    cudaFuncSetAttribute(k_attn, cudaFuncAttributeMaxDynamicSharedMemorySize, 67584);
    k_attn<<<288, 256, 67584>>>(qk, out);
}

// round 17
// speedup vs baseline: 2.2259x; 1.0875x over previous
#include <cuda_runtime.h>
#include <cuda_bf16.h>
#include <cstdint>

// ---------------- problem constants ----------------
// T=4, B=2, Ck=256, Cv=512, H=W=96, scales {1,2,3,6}, MAX=6, M=144, N=9216

// ---------------- device scratch (static, no allocation) ----------------
__device__ __align__(16) float g_pool6_k[2048 * 36];
__device__ __align__(16) float g_pool6_v[4096 * 36];
__device__ __align__(16) float g_convk[4 * 2 * 4 * 64 * 36];
__device__ __align__(16) float g_convv[4 * 2 * 4 * 128 * 36];
__device__ __align__(16) __nv_bfloat16 g_mkh[2 * 144 * 256];  // [b][m][c] hi (x Ck^-0.5)
__device__ __align__(16) __nv_bfloat16 g_mkl[2 * 144 * 256];  // lo
__device__ __align__(16) __nv_bfloat16 g_mvh[2 * 512 * 144];  // [b][v][m] hi
__device__ __align__(16) __nv_bfloat16 g_mvl[2 * 512 * 144];  // lo

__constant__ int c_scale[4] = {1, 2, 3, 6};
__constant__ int UI0[4][6] = {
    {0,0,0,0,0,0},
    {0,0,0,0,1,1},
    {0,0,0,1,1,2},
    {0,1,2,3,4,5}};
__constant__ int UI1[4][6] = {
    {0,0,0,0,0,0},
    {0,1,1,1,1,1},
    {0,1,1,2,2,2},
    {0,1,2,3,4,5}};
__constant__ float UW[4][6] = {
    {0.f,0.f,0.f,0.f,0.f,0.f},
    {0.f, 1.f/6.f, 0.5f, 5.f/6.f, 0.f, 0.f},
    {0.f, 0.25f, 0.75f, 0.25f, 0.75f, 0.f},
    {0.f,0.f,0.f,0.f,0.f,0.f}};

// ---------------- helpers ----------------
__device__ __forceinline__ void mma_bf16(float* d, const unsigned* a, const unsigned* b) {
    asm volatile(
        "mma.sync.aligned.m16n8k16.row.col.f32.bf16.bf16.f32 "
        "{%0,%1,%2,%3}, {%4,%5,%6,%7}, {%8,%9}, {%0,%1,%2,%3};"
        : "+f"(d[0]), "+f"(d[1]), "+f"(d[2]), "+f"(d[3])
        : "r"(a[0]), "r"(a[1]), "r"(a[2]), "r"(a[3]), "r"(b[0]), "r"(b[1]));
}
__device__ __forceinline__ void split_bf16(float x, __nv_bfloat16& hi, __nv_bfloat16& lo) {
    hi = __float2bfloat16(x);
    lo = __float2bfloat16(x - __bfloat162float(hi));
}
__device__ __forceinline__ unsigned packbf(__nv_bfloat16 l, __nv_bfloat16 h) {
    return ((unsigned)__bfloat16_as_ushort(h) << 16) | (unsigned)__bfloat16_as_ushort(l);
}

// ================= K1: 16x16 block means + qv passthrough copy =================
__global__ void k_pool(const float* __restrict__ mk, const float* __restrict__ mv,
                       const float* __restrict__ qv, float* __restrict__ out) {
    int p = blockIdx.x;
    int tid = threadIdx.x;
    if (p >= 6144) {
        int p2 = p - 6144;
        const float4* src = (const float4*)qv;
        float4* dst = (float4*)out;
        #pragma unroll
        for (int k = 0; k < 4; k++) {
            size_t f4 = (size_t)p2 * 1024 + tid + k * 256;
            size_t b = f4 / (512 * 2304);
            dst[f4 + b * 512 * 2304] = src[f4];
        }
        return;
    }
    const float* src; float* dst;
    if (p < 2048) { src = mk + (size_t)p * 9216; dst = g_pool6_k + (size_t)p * 36; }
    else { int q = p - 2048; src = mv + (size_t)q * 9216; dst = g_pool6_v + (size_t)q * 36; }
    __shared__ float rowsum[576];
    for (int task = tid; task < 576; task += 256) {
        int r = task / 6, j = task % 6;
        const float4* a = (const float4*)(src + r * 96 + j * 16);
        float4 v0 = a[0], v1 = a[1], v2 = a[2], v3 = a[3];
        rowsum[task] = (v0.x+v0.y+v0.z+v0.w) + (v1.x+v1.y+v1.z+v1.w)
                     + (v2.x+v2.y+v2.z+v2.w) + (v3.x+v3.y+v3.z+v3.w);
    }
    __syncthreads();
    if (tid < 36) {
        int by = tid / 6, bx = tid % 6;
        float s = 0.f;
        #pragma unroll
        for (int k = 0; k < 16; k++) s += rowsum[(by * 16 + k) * 6 + bx];
        dst[tid] = s * (1.0f / 256.0f);
    }
}

// ================= K2: per-(t,b,scale,pos) 1x1 conv + bias + relu (R14-proven) =================
__global__ void k_conv(const float* __restrict__ kw, const float* __restrict__ kb,
                       const float* __restrict__ vw, const float* __restrict__ vb) {
    __shared__ float pooled[512];
    int bi = blockIdx.x;
    int kv = bi / 400;
    int rem = bi % 400;
    int tb = rem / 50;
    int task = rem % 50;
    int si, pos;
    if (task < 1)       { si = 0; pos = 0; }
    else if (task < 5)  { si = 1; pos = task - 1; }
    else if (task < 14) { si = 2; pos = task - 5; }
    else                { si = 3; pos = task - 14; }
    int s = c_scale[si];
    int g = 6 / s;
    int pi = pos / s, pj = pos % s;
    int C  = kv ? 512 : 256;
    int Co = kv ? 128 : 64;
    const float* p6 = kv ? g_pool6_v : g_pool6_k;
    int tid = threadIdx.x;
    float ginv = 1.0f / (float)(g * g);
    for (int c = tid; c < C; c += 256) {
        const float* pp = p6 + (size_t)(tb * C + c) * 36;
        float sum = 0.f;
        for (int a = 0; a < g; a++)
            for (int bb = 0; bb < g; bb++)
                sum += pp[(pi * g + a) * 6 + (pj * g + bb)];
        pooled[c] = sum * ginv;
    }
    __syncthreads();
    int t = tb >> 1;
    int L = 256 / Co;
    int o = tid / L, r = tid % L;
    int chunk = C / L;
    const float* w = (kv ? vw : kw) + (size_t)((t * 4 + si) * Co + o) * C + r * chunk;
    const float* pl = pooled + r * chunk;
    float partial = 0.f;
    for (int i = 0; i < chunk; i += 4) {
        float4 wv = *(const float4*)(w + i);
        float4 pv = *(const float4*)(pl + i);
        partial += wv.x * pv.x + wv.y * pv.y + wv.z * pv.z + wv.w * pv.w;
    }
    for (int off = 1; off < L; off <<= 1)
        partial += __shfl_xor_sync(0xffffffffu, partial, off);
    if (r == 0) {
        float bias = (kv ? vb : kb)[(t * 4 + si) * Co + o];
        float v = fmaxf(partial + bias, 0.0f);
        float* cdst = (kv ? g_convv : g_convk) + (size_t)((tb * 4 + si) * Co + o) * 36 + pos;
        *cdst = v;
    }
}

// ================= K3: bilinear upsample + bf16 hi/lo layouts =================
__global__ void k_upsample() {
    int idx = blockIdx.x * 256 + threadIdx.x;
    if (idx >= 221184) return;
    if (idx < 73728) {
        int b = idx / (256 * 144);
        int rr = idx % (256 * 144);
        int c = rr / 144, m = rr % 144;
        int t = m / 36, pp = m % 36, i6 = pp / 6, j6 = pp % 6;
        int si = c >> 6, o = c & 63;
        int s = c_scale[si];
        const float* cv = g_convk + (size_t)(((t * 2 + b) * 4 + si) * 64 + o) * 36;
        int yi0 = UI0[si][i6], yi1 = UI1[si][i6]; float wy = UW[si][i6];
        int xi0 = UI0[si][j6], xi1 = UI1[si][j6]; float wx = UW[si][j6];
        float v00 = cv[yi0 * s + xi0], v01 = cv[yi0 * s + xi1];
        float v10 = cv[yi1 * s + xi0], v11 = cv[yi1 * s + xi1];
        float v = (1.f - wy) * ((1.f - wx) * v00 + wx * v01)
                +        wy  * ((1.f - wx) * v10 + wx * v11);
        v *= 0.0625f;
        __nv_bfloat16 hi, lo;
        split_bf16(v, hi, lo);
        size_t di = (size_t)(b * 144 + m) * 256 + c;
        g_mkh[di] = hi; g_mkl[di] = lo;
    } else {
        int r0 = idx - 73728;
        int b = r0 / (144 * 512);
        int rr = r0 % (144 * 512);
        int m = rr / 512, vch = rr % 512;
        int t = m / 36, pp = m % 36, i6 = pp / 6, j6 = pp % 6;
        int si = vch >> 7, o = vch & 127;
        int s = c_scale[si];
        const float* cv = g_convv + (size_t)(((t * 2 + b) * 4 + si) * 128 + o) * 36;
        int yi0 = UI0[si][i6], yi1 = UI1[si][i6]; float wy = UW[si][i6];
        int xi0 = UI0[si][j6], xi1 = UI1[si][j6]; float wx = UW[si][j6];
        float v00 = cv[yi0 * s + xi0], v01 = cv[yi0 * s + xi1];
        float v10 = cv[yi1 * s + xi0], v11 = cv[yi1 * s + xi1];
        float v = (1.f - wy) * ((1.f - wx) * v00 + wx * v01)
                +        wy  * ((1.f - wx) * v10 + wx * v11);
        __nv_bfloat16 hi, lo;
        split_bf16(v, hi, lo);
        size_t di = (size_t)(b * 512 + vch) * 144 + m;
        g_mvh[di] = hi; g_mvl[di] = lo;
    }
}

// ================= K4: tensor-core attention — R14 math, double-buffered, 1 bar/stage =================
// grid 144 = 2 b * 72 n-tiles of 128; 512 threads = 16 warps. Scalar frag loads (R14-proven).
//
// smem byte layout (total 135168):
//   QK phase : mkbuf[q] : hi @q*23040, lo @q*23040+11520       (q=0,1; pitch 40)
//              qkbuf[q] : hi @46080+q*20480, lo @+10240        (ends 87040)
//   AV phase : attT_hi @0      [128n][152m] 38912
//              attT_lo @38912               38912   (ends 77824)
//              mvbuf[q] : hi @77824+q*28672, lo @+14336        (ends 135168; pitch 56)
__global__ __launch_bounds__(512, 1)
void k_attn(const float* __restrict__ qk, float* __restrict__ out) {
    extern __shared__ char smem[];
    __nv_bfloat16* attT_hi = (__nv_bfloat16*)(smem);
    __nv_bfloat16* attT_lo = (__nv_bfloat16*)(smem + 38912);

    int tid = threadIdx.x;
    int w = tid >> 5, lane = tid & 31;
    int g = lane >> 2, tq = lane & 3;
    int b = blockIdx.x / 72, ntile = blockIdx.x % 72;
    int n0 = ntile * 128;

    const float* qkb = qk + (size_t)b * 256 * 9216 + n0;

    // ---------------- phase 1: QK scores ----------------
    float acc[9][4];
    #pragma unroll
    for (int i = 0; i < 9; i++)
        #pragma unroll
        for (int j = 0; j < 4; j++) acc[i][j] = 0.f;

    int qn = tid & 127;
    int cb = (tid >> 7) * 2;
    float qnext[8];
    uint4 mkreg[3];

    // prologue: LDG mk(0) + qk(0) into regs, STS into buf0, bar
    #pragma unroll
    for (int i = 0; i < 3; i++) {
        int q = tid + i * 512;
        if (q < 1152) {
            int hl = q / 576, rem = q % 576;
            int m = rem % 144, part = rem / 144;
            mkreg[i] = *(const uint4*)((hl ? g_mkl : g_mkh)
                       + ((size_t)(b * 144 + m)) * 256 + part * 8);
        }
    }
    #pragma unroll
    for (int i = 0; i < 4; i++) {
        int row = cb + i * 8;
        qnext[2*i]   = qkb[(size_t)row * 9216 + qn];
        qnext[2*i+1] = qkb[(size_t)(row + 1) * 9216 + qn];
    }
    #pragma unroll
    for (int i = 0; i < 3; i++) {
        int q = tid + i * 512;
        if (q < 1152) {
            int hl = q / 576, rem = q % 576;
            int m = rem % 144, part = rem / 144;
            *(uint4*)((__nv_bfloat16*)(smem + hl * 11520) + m * 40 + part * 8) = mkreg[i];
        }
    }
    #pragma unroll
    for (int i = 0; i < 4; i++) {
        int c0 = cb + i * 8;
        __nv_bfloat16 h0, l0, h1, l1;
        split_bf16(qnext[2*i], h0, l0);
        split_bf16(qnext[2*i+1], h1, l1);
        *(unsigned*)((__nv_bfloat16*)(smem + 46080) + qn * 40 + c0)         = packbf(h0, h1);
        *(unsigned*)((__nv_bfloat16*)(smem + 46080 + 10240) + qn * 40 + c0) = packbf(l0, l1);
    }
    __syncthreads();

    for (int cc = 0; cc < 8; cc++) {
        int cur = cc & 1, nxt = 1 - cur;
        const __nv_bfloat16* mk_hi = (const __nv_bfloat16*)(smem + cur * 23040);
        const __nv_bfloat16* mk_lo = (const __nv_bfloat16*)(smem + cur * 23040 + 11520);
        const __nv_bfloat16* qk_hi = (const __nv_bfloat16*)(smem + 46080 + cur * 20480);
        const __nv_bfloat16* qk_lo = (const __nv_bfloat16*)(smem + 46080 + cur * 20480 + 10240);
        // LDG next chunk into regs (hidden behind MMAs)
        if (cc < 7) {
            #pragma unroll
            for (int i = 0; i < 3; i++) {
                int q = tid + i * 512;
                if (q < 1152) {
                    int hl = q / 576, rem = q % 576;
                    int m = rem % 144, part = rem / 144;
                    mkreg[i] = *(const uint4*)((hl ? g_mkl : g_mkh)
                               + ((size_t)(b * 144 + m)) * 256 + (cc + 1) * 32 + part * 8);
                }
            }
            #pragma unroll
            for (int i = 0; i < 4; i++) {
                int row = (cc + 1) * 32 + cb + i * 8;
                qnext[2*i]   = qkb[(size_t)row * 9216 + qn];
                qnext[2*i+1] = qkb[(size_t)(row + 1) * 9216 + qn];
            }
        }
        // MMAs on buffer [cur] (R14 scalar addressing)
        #pragma unroll
        for (int kf = 0; kf < 2; kf++) {
            int kb0 = kf * 16 + 2 * tq;
            unsigned bh[2], bl[2];
            const __nv_bfloat16* brow = qk_hi + (w * 8 + g) * 40 + kb0;
            bh[0] = *(const unsigned*)(brow);
            bh[1] = *(const unsigned*)(brow + 8);
            const __nv_bfloat16* brol = qk_lo + (w * 8 + g) * 40 + kb0;
            bl[0] = *(const unsigned*)(brol);
            bl[1] = *(const unsigned*)(brol + 8);
            #pragma unroll
            for (int mf = 0; mf < 9; mf++) {
                const __nv_bfloat16* ah0 = mk_hi + (mf * 16 + g) * 40 + kb0;
                const __nv_bfloat16* al0 = mk_lo + (mf * 16 + g) * 40 + kb0;
                unsigned ah[4], al[4];
                ah[0] = *(const unsigned*)(ah0);
                ah[1] = *(const unsigned*)(ah0 + 8 * 40);
                ah[2] = *(const unsigned*)(ah0 + 8);
                ah[3] = *(const unsigned*)(ah0 + 8 * 40 + 8);
                al[0] = *(const unsigned*)(al0);
                al[1] = *(const unsigned*)(al0 + 8 * 40);
                al[2] = *(const unsigned*)(al0 + 8);
                al[3] = *(const unsigned*)(al0 + 8 * 40 + 8);
                mma_bf16(acc[mf], ah, bh);
                mma_bf16(acc[mf], ah, bl);
                mma_bf16(acc[mf], al, bh);
            }
        }
        // STS next chunk into buffer [nxt] (no pre-barrier: different buffer)
        if (cc < 7) {
            #pragma unroll
            for (int i = 0; i < 3; i++) {
                int q = tid + i * 512;
                if (q < 1152) {
                    int hl = q / 576, rem = q % 576;
                    int m = rem % 144, part = rem / 144;
                    *(uint4*)((__nv_bfloat16*)(smem + nxt * 23040 + hl * 11520)
                              + m * 40 + part * 8) = mkreg[i];
                }
            }
            #pragma unroll
            for (int i = 0; i < 4; i++) {
                int c0 = cb + i * 8;
                __nv_bfloat16 h0, l0, h1, l1;
                split_bf16(qnext[2*i], h0, l0);
                split_bf16(qnext[2*i+1], h1, l1);
                *(unsigned*)((__nv_bfloat16*)(smem + 46080 + nxt * 20480)
                             + qn * 40 + c0) = packbf(h0, h1);
                *(unsigned*)((__nv_bfloat16*)(smem + 46080 + nxt * 20480 + 10240)
                             + qn * 40 + c0) = packbf(l0, l1);
            }
        }
        __syncthreads();   // single barrier: buffer[nxt] full, buffer[cur] reads done
    }

    // ---------------- AV stage-0 LDG (overlaps softmax) ----------------
    uint4 mvreg[3];
    {
        #pragma unroll
        for (int it = 0; it < 3; it++) {
            int idx = tid + it * 512;
            int hl = idx / 768, rem = idx % 768;
            int r = rem / 6, part = rem % 6;
            int v = ((r >> 6) << 8) + (r & 63);   // p=0, ks=0
            mvreg[it] = *(const uint4*)((hl ? g_mvl : g_mvh)
                        + ((size_t)(b * 512 + v)) * 144 + part * 8);
        }
    }

    // ---------------- softmax over m (cols n = w*8 + 2tq + {0,1}) ----------------
    {
        float mx0 = -1e30f, mx1 = -1e30f;
        #pragma unroll
        for (int mf = 0; mf < 9; mf++) {
            mx0 = fmaxf(mx0, fmaxf(acc[mf][0], acc[mf][2]));
            mx1 = fmaxf(mx1, fmaxf(acc[mf][1], acc[mf][3]));
        }
        #pragma unroll
        for (int off = 4; off <= 16; off <<= 1) {
            mx0 = fmaxf(mx0, __shfl_xor_sync(0xffffffffu, mx0, off));
            mx1 = fmaxf(mx1, __shfl_xor_sync(0xffffffffu, mx1, off));
        }
        float s0 = 0.f, s1 = 0.f;
        #pragma unroll
        for (int mf = 0; mf < 9; mf++) {
            acc[mf][0] = __expf(acc[mf][0] - mx0);
            acc[mf][1] = __expf(acc[mf][1] - mx1);
            acc[mf][2] = __expf(acc[mf][2] - mx0);
            acc[mf][3] = __expf(acc[mf][3] - mx1);
            s0 += acc[mf][0] + acc[mf][2];
            s1 += acc[mf][1] + acc[mf][3];
        }
        #pragma unroll
        for (int off = 4; off <= 16; off <<= 1) {
            s0 += __shfl_xor_sync(0xffffffffu, s0, off);
            s1 += __shfl_xor_sync(0xffffffffu, s1, off);
        }
        float in0 = 1.0f / s0, in1 = 1.0f / s1;
        int ncol0 = w * 8 + 2 * tq, ncol1 = ncol0 + 1;
        #pragma unroll
        for (int mf = 0; mf < 9; mf++) {
            int m0 = mf * 16 + g, m1 = m0 + 8;
            __nv_bfloat16 hi, lo;
            split_bf16(acc[mf][0] * in0, hi, lo);
            attT_hi[ncol0 * 152 + m0] = hi; attT_lo[ncol0 * 152 + m0] = lo;
            split_bf16(acc[mf][1] * in1, hi, lo);
            attT_hi[ncol1 * 152 + m0] = hi; attT_lo[ncol1 * 152 + m0] = lo;
            split_bf16(acc[mf][2] * in0, hi, lo);
            attT_hi[ncol0 * 152 + m1] = hi; attT_lo[ncol0 * 152 + m1] = lo;
            split_bf16(acc[mf][3] * in1, hi, lo);
            attT_hi[ncol1 * 152 + m1] = hi; attT_lo[ncol1 * 152 + m1] = lo;
        }
    }

    // STS stage 0 into mv buf0
    #pragma unroll
    for (int it = 0; it < 3; it++) {
        int idx = tid + it * 512;
        int hl = idx / 768, rem = idx % 768;
        int r = rem / 6, part = rem % 6;
        *(uint4*)((__nv_bfloat16*)(smem + 77824 + hl * 14336) + r * 56 + part * 8) = mvreg[it];
    }
    __syncthreads();   // attT + mvch stage0 visible

    // ---------------- phase 2: AV, 12 stages of 48k, double-buffered, 1 bar/stage ----------------
    int mfa = w & 7;
    int vhalf = w >> 3;
    float acc2[8][4];
    for (int s = 0; s < 12; s++) {
        int p = s / 3, kq = s % 3, ks = kq * 48;
        int cur = s & 1, nxt = 1 - cur;
        if (kq == 0) {
            #pragma unroll
            for (int j = 0; j < 8; j++)
                #pragma unroll
                for (int q = 0; q < 4; q++) acc2[j][q] = 0.f;
        }
        // LDG next stage into regs (hidden behind MMAs)
        if (s < 11) {
            int p1 = (s + 1) / 3, ks1 = ((s + 1) % 3) * 48;
            #pragma unroll
            for (int it = 0; it < 3; it++) {
                int idx = tid + it * 512;
                int hl = idx / 768, rem = idx % 768;
                int r = rem / 6, part = rem % 6;
                int v = ((r >> 6) << 8) + p1 * 64 + (r & 63);
                mvreg[it] = *(const uint4*)((hl ? g_mvl : g_mvh)
                            + ((size_t)(b * 512 + v)) * 144 + ks1 + part * 8);
            }
        }
        // MMAs on buffer [cur]: 3 k-frags of 16 (scalar frag loads)
        {
            const __nv_bfloat16* mv_hi = (const __nv_bfloat16*)(smem + 77824 + cur * 28672);
            const __nv_bfloat16* mv_lo = (const __nv_bfloat16*)(smem + 77824 + cur * 28672 + 14336);
            #pragma unroll
            for (int kfi = 0; kfi < 3; kfi++) {
                int kb0 = ks + kfi * 16 + 2 * tq;          // absolute k for attT
                int kl0 = kfi * 16 + 2 * tq;               // stage-local k for mvch
                const __nv_bfloat16* ah0 = attT_hi + (mfa * 16 + g) * 152 + kb0;
                const __nv_bfloat16* al0 = attT_lo + (mfa * 16 + g) * 152 + kb0;
                unsigned ah[4], al[4];
                ah[0] = *(const unsigned*)(ah0);
                ah[1] = *(const unsigned*)(ah0 + 8 * 152);
                ah[2] = *(const unsigned*)(ah0 + 8);
                ah[3] = *(const unsigned*)(ah0 + 8 * 152 + 8);
                al[0] = *(const unsigned*)(al0);
                al[1] = *(const unsigned*)(al0 + 8 * 152);
                al[2] = *(const unsigned*)(al0 + 8);
                al[3] = *(const unsigned*)(al0 + 8 * 152 + 8);
                #pragma unroll
                for (int j = 0; j < 8; j++) {
                    int r = vhalf * 64 + j * 8 + g;
                    unsigned bh[2], bl[2];
                    const __nv_bfloat16* brow = mv_hi + r * 56 + kl0;
                    bh[0] = *(const unsigned*)(brow);
                    bh[1] = *(const unsigned*)(brow + 8);
                    const __nv_bfloat16* brol = mv_lo + r * 56 + kl0;
                    bl[0] = *(const unsigned*)(brol);
                    bl[1] = *(const unsigned*)(brol + 8);
                    mma_bf16(acc2[j], ah, bh);
                    mma_bf16(acc2[j], ah, bl);
                    mma_bf16(acc2[j], al, bh);
                }
            }
        }
        // STS next stage into buffer [nxt] (no pre-barrier: different buffer)
        if (s < 11) {
            #pragma unroll
            for (int it = 0; it < 3; it++) {
                int idx = tid + it * 512;
                int hl = idx / 768, rem = idx % 768;
                int r = rem / 6, part = rem % 6;
                *(uint4*)((__nv_bfloat16*)(smem + 77824 + nxt * 28672 + hl * 14336)
                          + r * 56 + part * 8) = mvreg[it];
            }
        }
        // epilogue at end of each p-pass (private gmem writes; no sync needed)
        if (kq == 2) {
            #pragma unroll
            for (int j = 0; j < 8; j++) {
                int v = vhalf * 256 + p * 64 + j * 8 + 2 * tq;
                float* p0 = out + (size_t)(b * 1024 + 512 + v) * 9216 + n0 + 16 * mfa + g;
                p0[0]        = acc2[j][0];
                p0[8]        = acc2[j][2];
                p0[9216]     = acc2[j][1];
                p0[9216 + 8] = acc2[j][3];
            }
        }
        if (s < 11) __syncthreads();   // single barrier: buf[nxt] full, buf[cur] reads done
    }
}

// ================= launch =================
extern "C" void kernel_launch(void* const* d_in, const int* in_sizes, int n_in,
                              void* d_out, int out_size) {
    const float* mk = (const float*)d_in[0];
    const float* mv = (const float*)d_in[1];
    const float* qk = (const float*)d_in[2];
    const float* qv = (const float*)d_in[3];
    const float* kw = (const float*)d_in[4];
    const float* kb = (const float*)d_in[5];
    const float* vw = (const float*)d_in[6];
    const float* vb = (const float*)d_in[7];
    float* out = (float*)d_out;

    // 2048 key planes + 4096 value planes + 2304 qv-copy blocks
    k_pool<<<8448, 256>>>(mk, mv, qv, out);
    k_conv<<<800, 256>>>(kw, kb, vw, vb);
    k_upsample<<<864, 256>>>();
    cudaFuncSetAttribute(k_attn, cudaFuncAttributeMaxDynamicSharedMemorySize, 135168);
    k_attn<<<144, 512, 135168>>>(qk, out);
}